// round 11
// baseline (speedup 1.0000x reference)
#include <cuda_runtime.h>
#include <cuda_bf16.h>

// ODEFunc: per-point fused MLP forward + analytic gradient.
// f32x2 packed (2 points/lane) x NPAIR=2 pair-slots; LDS.128 paired weights
// (one load feeds four FFMA2s). R11: f1 (the only long-lived activation
// array, 32 regs from early forward to the final gp loop) is staged in
// per-thread SMEM scratch, cutting peak live regs under 128 ->
// launch_bounds(128,4): 16 warps/SM (was 12 at 168 regs). DS factored out of
// the backward (R10), branch-free ELU, PW2T transposed backward scan,
// (f^2-1) sign cancellation, main net last.

using u64 = unsigned long long;

__device__ __forceinline__ u64 pk(float lo, float hi) {
    u64 r; asm("mov.b64 %0,{%1,%2};" : "=l"(r) : "f"(lo), "f"(hi)); return r;
}
__device__ __forceinline__ void upk(u64 v, float& lo, float& hi) {
    asm("mov.b64 {%0,%1},%2;" : "=f"(lo), "=f"(hi) : "l"(v));
}
__device__ __forceinline__ u64 fma2(u64 a, u64 b, u64 c) {
    u64 d; asm("fma.rn.f32x2 %0,%1,%2,%3;" : "=l"(d) : "l"(a), "l"(b), "l"(c)); return d;
}
__device__ __forceinline__ u64 mul2(u64 a, u64 b) {
    u64 d; asm("mul.rn.f32x2 %0,%1,%2;" : "=l"(d) : "l"(a), "l"(b)); return d;
}
__device__ __forceinline__ u64 add2(u64 a, u64 b) {
    u64 d; asm("add.rn.f32x2 %0,%1,%2;" : "=l"(d) : "l"(a), "l"(b)); return d;
}

#define MONE2 0xBF800000BF800000ULL  // (-1.0f, -1.0f)
#define HALF2 0x3F0000003F000000ULL  // ( 0.5f,  0.5f)

__device__ __forceinline__ float tanh_fast(float x) {
    float r; asm("tanh.approx.f32 %0,%1;" : "=f"(r) : "f"(x)); return r;
}
__device__ __forceinline__ float exp_fast(float x) {
    float r; asm("ex2.approx.f32 %0,%1;" : "=f"(r) : "f"(x * 1.4426950408889634f)); return r;
}
__device__ __forceinline__ float sigmoid_fast(float x) {
    return fmaf(0.5f, tanh_fast(0.5f * x), 0.5f);
}
__device__ __forceinline__ u64 tanh2(u64 v) {
    float a, b; upk(v, a, b);
    return pk(tanh_fast(a), tanh_fast(b));
}
// branch-free ELU: max(x, exp(min(x,0)) - 1); exact for x>0 since ex2(0)=1
__device__ __forceinline__ u64 elu2(u64 v) {
    float a, b; upk(v, a, b);
    a = fmaxf(a, exp_fast(fminf(a, 0.f)) - 1.f);
    b = fmaxf(b, exp_fast(fminf(b, 0.f)) - 1.f);
    return pk(a, b);
}

__device__ __forceinline__ ulonglong2 lds128(const u64* p) {
    return *reinterpret_cast<const ulonglong2*>(p);
}

#define NPAIR 2
#define NTHR 128

__global__ void __launch_bounds__(NTHR, 4)
odefunc_kernel(const float* __restrict__ x,
               const float* __restrict__ mW0, const float* __restrict__ mb0,
               const float* __restrict__ mW1, const float* __restrict__ mb1,
               const float* __restrict__ mW2, const float* __restrict__ mb2,
               const float* __restrict__ pW1, const float* __restrict__ pb1,
               const float* __restrict__ pW2, const float* __restrict__ pb2,
               const float* __restrict__ pW3, const float* __restrict__ pb3,
               float* __restrict__ out, int npairs)
{
    // [0..342): segmented weights (replicated f32x2); [344..472): PW2 transposed
    __shared__ __align__(16) u64 wsm[472];
    // f1 staging: [p*8+o][tid] -- per-thread, conflict-free (stride NTHR u64)
    __shared__ u64 f1s[NPAIR * 8 * NTHR];
    {
        const float* srcs[12] = {mW0, mb0, mW1, mb1, mW2, mb2,
                                 pW1, pb1, pW2, pb2, pW3, pb3};
        const int offs[13] = {0, 16, 24, 88, 96, 128, 132, 164, 180, 308, 324, 340, 342};
        for (int idx = threadIdx.x; idx < 342; idx += blockDim.x) {
            int seg = 0;
            #pragma unroll
            for (int s2 = 0; s2 < 12; s2++)
                if (idx >= offs[s2 + 1]) seg = s2 + 1;
            float w = srcs[seg][idx - offs[seg]];
            wsm[idx] = pk(w, w);
        }
        for (int idx = threadIdx.x; idx < 128; idx += blockDim.x) {
            int v = idx >> 6, rem = idx & 63;
            int pp = rem >> 3, q = rem & 7;
            float w = pW2[v * 64 + q * 8 + pp];
            wsm[344 + idx] = pk(w, w);
        }
    }
    __syncthreads();

    const u64* W0   = wsm;         // 16 : [i*2+j]
    const u64* B0   = wsm + 16;    // 8
    const u64* W1   = wsm + 24;    // 64 : [i*8+j]
    const u64* B1   = wsm + 88;    // 8
    const u64* W2   = wsm + 96;    // 32 : [i*8+j]
    const u64* B2   = wsm + 128;   // 4
    const u64* PW1  = wsm + 132;   // 32 : [v*16+o*2+i]
    const u64* PB1  = wsm + 164;   // 16 : [v*8+o]
    const u64* PW2  = wsm + 180;   // 128: [v*64+q*8+p]
    const u64* PB2  = wsm + 308;   // 16 : [v*8+q]
    const u64* PW3  = wsm + 324;   // 16 : [v*8+p]
    const u64* PB3  = wsm + 340;   // 2  : [v]
    const u64* PW2T = wsm + 344;   // 128: [v*64+p*8+q]

    const int tid = threadIdx.x;
    const int base   = blockIdx.x * NTHR + tid;
    const int stride = gridDim.x * NTHR;

    #define SCR(p, o) f1s[((p) * 8 + (o)) * NTHR + tid]

    int pi[NPAIR];
    bool valid[NPAIR];
    u64 X0[NPAIR], X1[NPAIR];
    #pragma unroll
    for (int p = 0; p < NPAIR; p++) {
        pi[p] = base + p * stride;
        valid[p] = pi[p] < npairs;
        if (valid[p]) {
            float4 xx = reinterpret_cast<const float4*>(x)[pi[p]];
            X0[p] = pk(xx.x, xx.z);
            X1[p] = pk(xx.y, xx.w);
        } else {
            X0[p] = 0ULL; X1[p] = 0ULL;
        }
    }

    // ================= p nets (NV=2), forward + analytic backward =================
    u64 G0[NPAIR], G1[NPAIR];
    #pragma unroll
    for (int p = 0; p < NPAIR; p++) { G0[p] = 0ULL; G1[p] = 0ULL; }

    #pragma unroll
    for (int v = 0; v < 2; v++) {
        // f1 = tanh(x @ pW1^T + pb1) -> smem staging (kills 32-reg long liveness)
        #pragma unroll
        for (int o = 0; o < 8; o++) {
            ulonglong2 w = lds128(&PW1[v * 16 + o * 2]);
            u64 b = PB1[v * 8 + o];
            #pragma unroll
            for (int p = 0; p < NPAIR; p++)
                SCR(p, o) = tanh2(fma2(X1[p], w.y, fma2(X0[p], w.x, b)));
        }

        // f2 = tanh(f1 @ pW2^T + pb2): pp-streaming over staged f1
        u64 f2[NPAIR][8];
        #pragma unroll
        for (int q = 0; q < 8; q++) {
            u64 b = PB2[v * 8 + q];
            #pragma unroll
            for (int p = 0; p < NPAIR; p++) f2[p][q] = b;
        }
        #pragma unroll
        for (int pp = 0; pp < 8; pp++) {
            u64 f1pp[NPAIR];
            #pragma unroll
            for (int p = 0; p < NPAIR; p++) f1pp[p] = SCR(p, pp);
            #pragma unroll
            for (int q = 0; q < 8; q += 2) {
                // contiguous along q via PW2T: one LDS.128 = weights for q,q+1
                ulonglong2 w = lds128(&PW2T[v * 64 + pp * 8 + q]);
                #pragma unroll
                for (int p = 0; p < NPAIR; p++) {
                    f2[p][q]     = fma2(f1pp[p], w.x, f2[p][q]);
                    f2[p][q + 1] = fma2(f1pp[p], w.y, f2[p][q + 1]);
                }
            }
        }
        #pragma unroll
        for (int q = 0; q < 8; q++)
            #pragma unroll
            for (int p = 0; p < NPAIR; p++)
                f2[p][q] = tanh2(f2[p][q]);

        // z = f2 . pW3 + pb3 ; s = sigma(sigma(z)) ; DS = s(1-s)
        u64 DS[NPAIR];
        {
            u64 a0[NPAIR], a1[NPAIR];
            u64 b = PB3[v];
            #pragma unroll
            for (int p = 0; p < NPAIR; p++) { a0[p] = b; a1[p] = 0ULL; }
            #pragma unroll
            for (int pp = 0; pp < 8; pp += 2) {
                ulonglong2 w = lds128(&PW3[v * 8 + pp]);
                #pragma unroll
                for (int p = 0; p < NPAIR; p++) {
                    a0[p] = fma2(f2[p][pp],     w.x, a0[p]);
                    a1[p] = fma2(f2[p][pp + 1], w.y, a1[p]);
                }
            }
            #pragma unroll
            for (int p = 0; p < NPAIR; p++) {
                float za, zb; upk(add2(a0[p], a1[p]), za, zb);
                float sa = sigmoid_fast(sigmoid_fast(za));
                float sb = sigmoid_fast(sigmoid_fast(zb));
                DS[p] = pk(sa * (1.f - sa), sb * (1.f - sb));
            }
        }

        // gq'_q = w3_q * (f2_q^2 - 1)  (DS factored out; sign cancels with gp)
        #pragma unroll
        for (int q = 0; q < 8; q += 2) {
            ulonglong2 w3 = lds128(&PW3[v * 8 + q]);
            #pragma unroll
            for (int p = 0; p < NPAIR; p++) {
                u64 u2a = fma2(f2[p][q],     f2[p][q],     MONE2);
                u64 u2b = fma2(f2[p][q + 1], f2[p][q + 1], MONE2);
                f2[p][q]     = mul2(w3.x, u2a);
                f2[p][q + 1] = mul2(w3.y, u2b);
            }
        }

        // PG_p = sum_pp [(sum_q gq'_q W2[q,pp]) * (f1_pp^2-1)] * pW1[pp,:]
        u64 PG0[NPAIR], PG1[NPAIR];
        #pragma unroll
        for (int p = 0; p < NPAIR; p++) { PG0[p] = 0ULL; PG1[p] = 0ULL; }
        #pragma unroll
        for (int pp = 0; pp < 8; pp++) {
            u64 a0[NPAIR], a1[NPAIR];
            #pragma unroll
            for (int p = 0; p < NPAIR; p++) { a0[p] = 0ULL; a1[p] = 0ULL; }
            #pragma unroll
            for (int q = 0; q < 8; q += 2) {
                ulonglong2 w = lds128(&PW2T[v * 64 + pp * 8 + q]);
                #pragma unroll
                for (int p = 0; p < NPAIR; p++) {
                    a0[p] = fma2(f2[p][q],     w.x, a0[p]);
                    a1[p] = fma2(f2[p][q + 1], w.y, a1[p]);
                }
            }
            ulonglong2 w1p = lds128(&PW1[v * 16 + pp * 2]);
            #pragma unroll
            for (int p = 0; p < NPAIR; p++) {
                u64 f1pp = SCR(p, pp);              // reload staged f1
                u64 u1 = fma2(f1pp, f1pp, MONE2);
                u64 gpv = mul2(add2(a0[p], a1[p]), u1);
                PG0[p] = fma2(gpv, w1p.x, PG0[p]);
                PG1[p] = fma2(gpv, w1p.y, PG1[p]);
            }
        }
        // fold DS in once per v
        #pragma unroll
        for (int p = 0; p < NPAIR; p++) {
            G0[p] = fma2(DS[p], PG0[p], G0[p]);
            G1[p] = fma2(DS[p], PG1[p], G1[p]);
        }
    }

    // ================= main net (last: only G carried across) =================
    u64 m2v[NPAIR], magA[NPAIR], magD[NPAIR];
    {
        // h0 -> staging (same scratch, f1 dead now)
        #pragma unroll
        for (int i = 0; i < 8; i++) {
            ulonglong2 w = lds128(&W0[i * 2]);
            u64 b = B0[i];
            #pragma unroll
            for (int p = 0; p < NPAIR; p++)
                SCR(p, i) = elu2(fma2(X1[p], w.y, fma2(X0[p], w.x, b)));
        }

        // h1: j-streaming over staged h0 (W1 column-contiguous? need transpose-free:
        // W1[i*8+j] scanned along i for fixed j is stride-8 -> instead scan along j
        // per i with pairwise loads, pulling h0 from scratch once per (i,j) pair)
        u64 h1[NPAIR][8];
        #pragma unroll
        for (int i = 0; i < 8; i++) {
            u64 a0[NPAIR], a1[NPAIR];
            u64 b = B1[i];
            #pragma unroll
            for (int p = 0; p < NPAIR; p++) { a0[p] = b; a1[p] = 0ULL; }
            #pragma unroll
            for (int j = 0; j < 8; j += 2) {
                ulonglong2 w = lds128(&W1[i * 8 + j]);
                u64 h0a[NPAIR], h0b[NPAIR];
                #pragma unroll
                for (int p = 0; p < NPAIR; p++) {
                    h0a[p] = SCR(p, j);
                    h0b[p] = SCR(p, j + 1);
                }
                #pragma unroll
                for (int p = 0; p < NPAIR; p++) {
                    a0[p] = fma2(h0a[p], w.x, a0[p]);
                    a1[p] = fma2(h0b[p], w.y, a1[p]);
                }
            }
            #pragma unroll
            for (int p = 0; p < NPAIR; p++) h1[p][i] = elu2(add2(a0[p], a1[p]));
        }

        u64 bb[NPAIR][4];
        #pragma unroll
        for (int i = 0; i < 4; i++) {
            u64 a0[NPAIR], a1[NPAIR];
            u64 b = B2[i];
            #pragma unroll
            for (int p = 0; p < NPAIR; p++) { a0[p] = b; a1[p] = 0ULL; }
            #pragma unroll
            for (int j = 0; j < 8; j += 2) {
                ulonglong2 w = lds128(&W2[i * 8 + j]);
                #pragma unroll
                for (int p = 0; p < NPAIR; p++) {
                    a0[p] = fma2(h1[p][j],     w.x, a0[p]);
                    a1[p] = fma2(h1[p][j + 1], w.y, a1[p]);
                }
            }
            #pragma unroll
            for (int p = 0; p < NPAIR; p++) bb[p][i] = add2(a0[p], a1[p]);
        }
        #pragma unroll
        for (int p = 0; p < NPAIR; p++) {
            m2v[p]  = fma2(bb[p][0], bb[p][1], mul2(bb[p][2], bb[p][3]));
            magA[p] = fma2(bb[p][0], bb[p][0], mul2(bb[p][2], bb[p][2]));
            magD[p] = fma2(bb[p][1], bb[p][1], mul2(bb[p][3], bb[p][3]));
        }
    }

    // out0 = 0.5*(magA*G0 + m2*G1); out1 = 0.5*(m2*G0 + magD*G1)
    #pragma unroll
    for (int p = 0; p < NPAIR; p++) {
        if (!valid[p]) continue;
        u64 o0 = mul2(HALF2, fma2(magA[p], G0[p], mul2(m2v[p], G1[p])));
        u64 o1 = mul2(HALF2, fma2(m2v[p], G0[p], mul2(magD[p], G1[p])));
        float a0, b0c, a1, b1c;
        upk(o0, a0, b0c);
        upk(o1, a1, b1c);
        reinterpret_cast<float4*>(out)[pi[p]] = make_float4(a0, a1, b0c, b1c);
    }
}

extern "C" void kernel_launch(void* const* d_in, const int* in_sizes, int n_in,
                              void* d_out, int out_size)
{
    const float* x   = (const float*)d_in[1];
    const float* mW0 = (const float*)d_in[2];
    const float* mb0 = (const float*)d_in[3];
    const float* mW1 = (const float*)d_in[4];
    const float* mb1 = (const float*)d_in[5];
    const float* mW2 = (const float*)d_in[6];
    const float* mb2 = (const float*)d_in[7];
    const float* pW1 = (const float*)d_in[8];
    const float* pb1 = (const float*)d_in[9];
    const float* pW2 = (const float*)d_in[10];
    const float* pb2 = (const float*)d_in[11];
    const float* pW3 = (const float*)d_in[12];
    const float* pb3 = (const float*)d_in[13];

    int B = in_sizes[1] / 2;       // x is (B, 2)
    int npairs = B / 2;
    int threads = NTHR;
    int tot_threads = (npairs + NPAIR - 1) / NPAIR;
    int blocks = (tot_threads + threads - 1) / threads;

    odefunc_kernel<<<blocks, threads>>>(x, mW0, mb0, mW1, mb1, mW2, mb2,
                                        pW1, pb1, pW2, pb2, pW3, pb3,
                                        (float*)d_out, npairs);
}

// round 12
// speedup vs baseline: 2.5129x; 2.5129x over previous
#include <cuda_runtime.h>
#include <cuda_bf16.h>

// ODEFunc: per-point fused MLP forward + analytic gradient.
// R10 design point (NPAIR=2, LDS.128 paired weights, DS factored backward,
// branch-free ELU, 168 regs / 12 warps per SM) + R12: WARP PHASE STAGGER.
// Even warps run p-nets then main-net; odd warps the reverse. Lockstepped
// warps otherwise serialize their MUFU-heavy phases (tanh/ELU, rt=8/SMSP)
// against each other while the FMA pipe idles; the stagger overlaps a
// MUFU-phase warp with an FMA-phase warp on the same scheduler.

using u64 = unsigned long long;

__device__ __forceinline__ u64 pk(float lo, float hi) {
    u64 r; asm("mov.b64 %0,{%1,%2};" : "=l"(r) : "f"(lo), "f"(hi)); return r;
}
__device__ __forceinline__ void upk(u64 v, float& lo, float& hi) {
    asm("mov.b64 {%0,%1},%2;" : "=f"(lo), "=f"(hi) : "l"(v));
}
__device__ __forceinline__ u64 fma2(u64 a, u64 b, u64 c) {
    u64 d; asm("fma.rn.f32x2 %0,%1,%2,%3;" : "=l"(d) : "l"(a), "l"(b), "l"(c)); return d;
}
__device__ __forceinline__ u64 mul2(u64 a, u64 b) {
    u64 d; asm("mul.rn.f32x2 %0,%1,%2;" : "=l"(d) : "l"(a), "l"(b)); return d;
}
__device__ __forceinline__ u64 add2(u64 a, u64 b) {
    u64 d; asm("add.rn.f32x2 %0,%1,%2;" : "=l"(d) : "l"(a), "l"(b)); return d;
}

#define MONE2 0xBF800000BF800000ULL  // (-1.0f, -1.0f)
#define HALF2 0x3F0000003F000000ULL  // ( 0.5f,  0.5f)

__device__ __forceinline__ float tanh_fast(float x) {
    float r; asm("tanh.approx.f32 %0,%1;" : "=f"(r) : "f"(x)); return r;
}
__device__ __forceinline__ float exp_fast(float x) {
    float r; asm("ex2.approx.f32 %0,%1;" : "=f"(r) : "f"(x * 1.4426950408889634f)); return r;
}
__device__ __forceinline__ float sigmoid_fast(float x) {
    return fmaf(0.5f, tanh_fast(0.5f * x), 0.5f);
}
__device__ __forceinline__ u64 tanh2(u64 v) {
    float a, b; upk(v, a, b);
    return pk(tanh_fast(a), tanh_fast(b));
}
// branch-free ELU: max(x, exp(min(x,0)) - 1); exact for x>0 since ex2(0)=1
__device__ __forceinline__ u64 elu2(u64 v) {
    float a, b; upk(v, a, b);
    a = fmaxf(a, exp_fast(fminf(a, 0.f)) - 1.f);
    b = fmaxf(b, exp_fast(fminf(b, 0.f)) - 1.f);
    return pk(a, b);
}

__device__ __forceinline__ ulonglong2 lds128(const u64* p) {
    return *reinterpret_cast<const ulonglong2*>(p);
}

#define NPAIR 2
#define NTHR 128

// ---- p nets (NV=2): forward + analytic backward. Accumulates into G0/G1. ----
__device__ __forceinline__ void pnets(
    const u64* __restrict__ PW1, const u64* __restrict__ PB1,
    const u64* __restrict__ PW2, const u64* __restrict__ PB2,
    const u64* __restrict__ PW3, const u64* __restrict__ PB3,
    const u64* __restrict__ PW2T,
    const u64 X0[NPAIR], const u64 X1[NPAIR],
    u64 G0[NPAIR], u64 G1[NPAIR])
{
    #pragma unroll
    for (int v = 0; v < 2; v++) {
        // f1 = tanh(x @ pW1^T + pb1)
        u64 f1[NPAIR][8];
        #pragma unroll
        for (int o = 0; o < 8; o++) {
            ulonglong2 w = lds128(&PW1[v * 16 + o * 2]);
            u64 b = PB1[v * 8 + o];
            #pragma unroll
            for (int p = 0; p < NPAIR; p++)
                f1[p][o] = tanh2(fma2(X1[p], w.y, fma2(X0[p], w.x, b)));
        }

        // f2 = tanh(f1 @ pW2^T + pb2)
        u64 f2[NPAIR][8];
        #pragma unroll
        for (int q = 0; q < 8; q++) {
            u64 a0[NPAIR], a1[NPAIR];
            u64 b = PB2[v * 8 + q];
            #pragma unroll
            for (int p = 0; p < NPAIR; p++) { a0[p] = b; a1[p] = 0ULL; }
            #pragma unroll
            for (int pp = 0; pp < 8; pp += 2) {
                ulonglong2 w = lds128(&PW2[v * 64 + q * 8 + pp]);
                #pragma unroll
                for (int p = 0; p < NPAIR; p++) {
                    a0[p] = fma2(f1[p][pp],     w.x, a0[p]);
                    a1[p] = fma2(f1[p][pp + 1], w.y, a1[p]);
                }
            }
            #pragma unroll
            for (int p = 0; p < NPAIR; p++) f2[p][q] = tanh2(add2(a0[p], a1[p]));
        }

        // z = f2 . pW3 + pb3 ; s = sigma(sigma(z)) ; DS = s(1-s)
        u64 DS[NPAIR];
        {
            u64 a0[NPAIR], a1[NPAIR];
            u64 b = PB3[v];
            #pragma unroll
            for (int p = 0; p < NPAIR; p++) { a0[p] = b; a1[p] = 0ULL; }
            #pragma unroll
            for (int pp = 0; pp < 8; pp += 2) {
                ulonglong2 w = lds128(&PW3[v * 8 + pp]);
                #pragma unroll
                for (int p = 0; p < NPAIR; p++) {
                    a0[p] = fma2(f2[p][pp],     w.x, a0[p]);
                    a1[p] = fma2(f2[p][pp + 1], w.y, a1[p]);
                }
            }
            #pragma unroll
            for (int p = 0; p < NPAIR; p++) {
                float za, zb; upk(add2(a0[p], a1[p]), za, zb);
                float sa = sigmoid_fast(sigmoid_fast(za));
                float sb = sigmoid_fast(sigmoid_fast(zb));
                DS[p] = pk(sa * (1.f - sa), sb * (1.f - sb));
            }
        }

        // gq'_q = w3_q * (f2_q^2 - 1)  (DS factored out; sign cancels with gp)
        #pragma unroll
        for (int q = 0; q < 8; q += 2) {
            ulonglong2 w3 = lds128(&PW3[v * 8 + q]);
            #pragma unroll
            for (int p = 0; p < NPAIR; p++) {
                u64 u2a = fma2(f2[p][q],     f2[p][q],     MONE2);
                u64 u2b = fma2(f2[p][q + 1], f2[p][q + 1], MONE2);
                f2[p][q]     = mul2(w3.x, u2a);
                f2[p][q + 1] = mul2(w3.y, u2b);
            }
        }

        // PG_p = sum_pp [(sum_q gq'_q W2[q,pp]) * (f1_pp^2-1)] * pW1[pp,:]
        u64 PG0[NPAIR], PG1[NPAIR];
        #pragma unroll
        for (int p = 0; p < NPAIR; p++) { PG0[p] = 0ULL; PG1[p] = 0ULL; }
        #pragma unroll
        for (int pp = 0; pp < 8; pp++) {
            u64 a0[NPAIR], a1[NPAIR];
            #pragma unroll
            for (int p = 0; p < NPAIR; p++) { a0[p] = 0ULL; a1[p] = 0ULL; }
            #pragma unroll
            for (int q = 0; q < 8; q += 2) {
                ulonglong2 w = lds128(&PW2T[v * 64 + pp * 8 + q]);
                #pragma unroll
                for (int p = 0; p < NPAIR; p++) {
                    a0[p] = fma2(f2[p][q],     w.x, a0[p]);
                    a1[p] = fma2(f2[p][q + 1], w.y, a1[p]);
                }
            }
            ulonglong2 w1p = lds128(&PW1[v * 16 + pp * 2]);
            #pragma unroll
            for (int p = 0; p < NPAIR; p++) {
                u64 u1 = fma2(f1[p][pp], f1[p][pp], MONE2);
                u64 gpv = mul2(add2(a0[p], a1[p]), u1);
                PG0[p] = fma2(gpv, w1p.x, PG0[p]);
                PG1[p] = fma2(gpv, w1p.y, PG1[p]);
            }
        }
        #pragma unroll
        for (int p = 0; p < NPAIR; p++) {
            G0[p] = fma2(DS[p], PG0[p], G0[p]);
            G1[p] = fma2(DS[p], PG1[p], G1[p]);
        }
    }
}

// ---- main net: produces m2v / magA / magD ----
__device__ __forceinline__ void mainnet(
    const u64* __restrict__ W0, const u64* __restrict__ B0,
    const u64* __restrict__ W1, const u64* __restrict__ B1,
    const u64* __restrict__ W2, const u64* __restrict__ B2,
    const u64 X0[NPAIR], const u64 X1[NPAIR],
    u64 m2v[NPAIR], u64 magA[NPAIR], u64 magD[NPAIR])
{
    u64 h0[NPAIR][8];
    #pragma unroll
    for (int i = 0; i < 8; i++) {
        ulonglong2 w = lds128(&W0[i * 2]);
        u64 b = B0[i];
        #pragma unroll
        for (int p = 0; p < NPAIR; p++)
            h0[p][i] = elu2(fma2(X1[p], w.y, fma2(X0[p], w.x, b)));
    }

    u64 h1[NPAIR][8];
    #pragma unroll
    for (int i = 0; i < 8; i++) {
        u64 a0[NPAIR], a1[NPAIR];
        u64 b = B1[i];
        #pragma unroll
        for (int p = 0; p < NPAIR; p++) { a0[p] = b; a1[p] = 0ULL; }
        #pragma unroll
        for (int j = 0; j < 8; j += 2) {
            ulonglong2 w = lds128(&W1[i * 8 + j]);
            #pragma unroll
            for (int p = 0; p < NPAIR; p++) {
                a0[p] = fma2(h0[p][j],     w.x, a0[p]);
                a1[p] = fma2(h0[p][j + 1], w.y, a1[p]);
            }
        }
        #pragma unroll
        for (int p = 0; p < NPAIR; p++) h1[p][i] = elu2(add2(a0[p], a1[p]));
    }

    u64 bb[NPAIR][4];
    #pragma unroll
    for (int i = 0; i < 4; i++) {
        u64 a0[NPAIR], a1[NPAIR];
        u64 b = B2[i];
        #pragma unroll
        for (int p = 0; p < NPAIR; p++) { a0[p] = b; a1[p] = 0ULL; }
        #pragma unroll
        for (int j = 0; j < 8; j += 2) {
            ulonglong2 w = lds128(&W2[i * 8 + j]);
            #pragma unroll
            for (int p = 0; p < NPAIR; p++) {
                a0[p] = fma2(h1[p][j],     w.x, a0[p]);
                a1[p] = fma2(h1[p][j + 1], w.y, a1[p]);
            }
        }
        #pragma unroll
        for (int p = 0; p < NPAIR; p++) bb[p][i] = add2(a0[p], a1[p]);
    }
    #pragma unroll
    for (int p = 0; p < NPAIR; p++) {
        m2v[p]  = fma2(bb[p][0], bb[p][1], mul2(bb[p][2], bb[p][3]));
        magA[p] = fma2(bb[p][0], bb[p][0], mul2(bb[p][2], bb[p][2]));
        magD[p] = fma2(bb[p][1], bb[p][1], mul2(bb[p][3], bb[p][3]));
    }
}

__global__ void __launch_bounds__(NTHR, 3)
odefunc_kernel(const float* __restrict__ x,
               const float* __restrict__ mW0, const float* __restrict__ mb0,
               const float* __restrict__ mW1, const float* __restrict__ mb1,
               const float* __restrict__ mW2, const float* __restrict__ mb2,
               const float* __restrict__ pW1, const float* __restrict__ pb1,
               const float* __restrict__ pW2, const float* __restrict__ pb2,
               const float* __restrict__ pW3, const float* __restrict__ pb3,
               float* __restrict__ out, int npairs)
{
    // [0..342): segmented weights (replicated f32x2); [344..472): PW2 transposed
    __shared__ __align__(16) u64 wsm[472];
    {
        const float* srcs[12] = {mW0, mb0, mW1, mb1, mW2, mb2,
                                 pW1, pb1, pW2, pb2, pW3, pb3};
        const int offs[13] = {0, 16, 24, 88, 96, 128, 132, 164, 180, 308, 324, 340, 342};
        for (int idx = threadIdx.x; idx < 342; idx += blockDim.x) {
            int seg = 0;
            #pragma unroll
            for (int s2 = 0; s2 < 12; s2++)
                if (idx >= offs[s2 + 1]) seg = s2 + 1;
            float w = srcs[seg][idx - offs[seg]];
            wsm[idx] = pk(w, w);
        }
        for (int idx = threadIdx.x; idx < 128; idx += blockDim.x) {
            int v = idx >> 6, rem = idx & 63;
            int pp = rem >> 3, q = rem & 7;
            float w = pW2[v * 64 + q * 8 + pp];
            wsm[344 + idx] = pk(w, w);
        }
    }
    __syncthreads();

    const u64* W0   = wsm;         // 16 : [i*2+j]
    const u64* B0   = wsm + 16;    // 8
    const u64* W1   = wsm + 24;    // 64 : [i*8+j]
    const u64* B1   = wsm + 88;    // 8
    const u64* W2   = wsm + 96;    // 32 : [i*8+j]
    const u64* B2   = wsm + 128;   // 4
    const u64* PW1  = wsm + 132;   // 32 : [v*16+o*2+i]
    const u64* PB1  = wsm + 164;   // 16 : [v*8+o]
    const u64* PW2  = wsm + 180;   // 128: [v*64+q*8+p]
    const u64* PB2  = wsm + 308;   // 16 : [v*8+q]
    const u64* PW3  = wsm + 324;   // 16 : [v*8+p]
    const u64* PB3  = wsm + 340;   // 2  : [v]
    const u64* PW2T = wsm + 344;   // 128: [v*64+p*8+q]

    const int tid = threadIdx.x;
    const int base   = blockIdx.x * NTHR + tid;
    const int stride = gridDim.x * NTHR;

    int pi[NPAIR];
    bool valid[NPAIR];
    u64 X0[NPAIR], X1[NPAIR];
    #pragma unroll
    for (int p = 0; p < NPAIR; p++) {
        pi[p] = base + p * stride;
        valid[p] = pi[p] < npairs;
        if (valid[p]) {
            float4 xx = reinterpret_cast<const float4*>(x)[pi[p]];
            X0[p] = pk(xx.x, xx.z);
            X1[p] = pk(xx.y, xx.w);
        } else {
            X0[p] = 0ULL; X1[p] = 0ULL;
        }
    }

    u64 G0[NPAIR], G1[NPAIR];
    #pragma unroll
    for (int p = 0; p < NPAIR; p++) { G0[p] = 0ULL; G1[p] = 0ULL; }
    u64 m2v[NPAIR], magA[NPAIR], magD[NPAIR];

    // Warp phase stagger: even warps p-nets first, odd warps main-net first.
    if ((tid & 32) == 0) {
        pnets(PW1, PB1, PW2, PB2, PW3, PB3, PW2T, X0, X1, G0, G1);
        mainnet(W0, B0, W1, B1, W2, B2, X0, X1, m2v, magA, magD);
    } else {
        mainnet(W0, B0, W1, B1, W2, B2, X0, X1, m2v, magA, magD);
        pnets(PW1, PB1, PW2, PB2, PW3, PB3, PW2T, X0, X1, G0, G1);
    }

    // out0 = 0.5*(magA*G0 + m2*G1); out1 = 0.5*(m2*G0 + magD*G1)
    #pragma unroll
    for (int p = 0; p < NPAIR; p++) {
        if (!valid[p]) continue;
        u64 o0 = mul2(HALF2, fma2(magA[p], G0[p], mul2(m2v[p], G1[p])));
        u64 o1 = mul2(HALF2, fma2(m2v[p], G0[p], mul2(magD[p], G1[p])));
        float a0, b0c, a1, b1c;
        upk(o0, a0, b0c);
        upk(o1, a1, b1c);
        reinterpret_cast<float4*>(out)[pi[p]] = make_float4(a0, a1, b0c, b1c);
    }
}

extern "C" void kernel_launch(void* const* d_in, const int* in_sizes, int n_in,
                              void* d_out, int out_size)
{
    const float* x   = (const float*)d_in[1];
    const float* mW0 = (const float*)d_in[2];
    const float* mb0 = (const float*)d_in[3];
    const float* mW1 = (const float*)d_in[4];
    const float* mb1 = (const float*)d_in[5];
    const float* mW2 = (const float*)d_in[6];
    const float* mb2 = (const float*)d_in[7];
    const float* pW1 = (const float*)d_in[8];
    const float* pb1 = (const float*)d_in[9];
    const float* pW2 = (const float*)d_in[10];
    const float* pb2 = (const float*)d_in[11];
    const float* pW3 = (const float*)d_in[12];
    const float* pb3 = (const float*)d_in[13];

    int B = in_sizes[1] / 2;       // x is (B, 2)
    int npairs = B / 2;
    int threads = NTHR;
    int tot_threads = (npairs + NPAIR - 1) / NPAIR;
    int blocks = (tot_threads + threads - 1) / threads;

    odefunc_kernel<<<blocks, threads>>>(x, mW0, mb0, mW1, mb1, mW2, mb2,
                                        pW1, pb1, pW2, pb2, pW3, pb3,
                                        (float*)d_out, npairs);
}

// round 13
// speedup vs baseline: 3.2865x; 1.3079x over previous
#include <cuda_runtime.h>
#include <cuda_bf16.h>

// ODEFunc: per-point fused MLP forward + analytic gradient.
// R10 design point (best: 61.9us): NPAIR=2 pair-slots x f32x2 (4 points per
// thread), LDS.128 paired weights (one load feeds four FFMA2s), DS factored
// backward, branch-free ELU, 168 regs / 12 warps per SM, main net last.
// R13 trims (algebraic, zero structural change):
//  - PW2T pre-scaled by w3 at fill time -> gq is one in-place fma2 (-32 mul2)
//  - s(1-s) = 0.25(1-tanh^2(f3/2)) identity -> shorter DS chain
//  - mean-0.5 folded into DS -> no HALF2 mul2 in epilogue

using u64 = unsigned long long;

__device__ __forceinline__ u64 pk(float lo, float hi) {
    u64 r; asm("mov.b64 %0,{%1,%2};" : "=l"(r) : "f"(lo), "f"(hi)); return r;
}
__device__ __forceinline__ void upk(u64 v, float& lo, float& hi) {
    asm("mov.b64 {%0,%1},%2;" : "=f"(lo), "=f"(hi) : "l"(v));
}
__device__ __forceinline__ u64 fma2(u64 a, u64 b, u64 c) {
    u64 d; asm("fma.rn.f32x2 %0,%1,%2,%3;" : "=l"(d) : "l"(a), "l"(b), "l"(c)); return d;
}
__device__ __forceinline__ u64 mul2(u64 a, u64 b) {
    u64 d; asm("mul.rn.f32x2 %0,%1,%2;" : "=l"(d) : "l"(a), "l"(b)); return d;
}
__device__ __forceinline__ u64 add2(u64 a, u64 b) {
    u64 d; asm("add.rn.f32x2 %0,%1,%2;" : "=l"(d) : "l"(a), "l"(b)); return d;
}

#define MONE2 0xBF800000BF800000ULL  // (-1.0f, -1.0f)

__device__ __forceinline__ float tanh_fast(float x) {
    float r; asm("tanh.approx.f32 %0,%1;" : "=f"(r) : "f"(x)); return r;
}
__device__ __forceinline__ float exp_fast(float x) {
    float r; asm("ex2.approx.f32 %0,%1;" : "=f"(r) : "f"(x * 1.4426950408889634f)); return r;
}
__device__ __forceinline__ u64 tanh2(u64 v) {
    float a, b; upk(v, a, b);
    return pk(tanh_fast(a), tanh_fast(b));
}
// branch-free ELU: max(x, exp(min(x,0)) - 1); exact for x>0 since ex2(0)=1
__device__ __forceinline__ u64 elu2(u64 v) {
    float a, b; upk(v, a, b);
    a = fmaxf(a, exp_fast(fminf(a, 0.f)) - 1.f);
    b = fmaxf(b, exp_fast(fminf(b, 0.f)) - 1.f);
    return pk(a, b);
}
// DS including the mean-1/2: s = sigma(f3), f3 = sigma(z);
// s(1-s) = 0.25*(1 - t2^2), t2 = tanh(f3/2), f3/2 = 0.25*tanh(z/2) + 0.25
// -> ds = 0.125*(1 - t2^2)
__device__ __forceinline__ float ds_half(float z) {
    float t1 = tanh_fast(0.5f * z);
    float t2 = tanh_fast(fmaf(0.25f, t1, 0.25f));
    return fmaf(t2 * t2, -0.125f, 0.125f);
}

__device__ __forceinline__ ulonglong2 lds128(const u64* p) {
    return *reinterpret_cast<const ulonglong2*>(p);
}

#define NPAIR 2
#define NTHR 128

__global__ void __launch_bounds__(NTHR, 3)
odefunc_kernel(const float* __restrict__ x,
               const float* __restrict__ mW0, const float* __restrict__ mb0,
               const float* __restrict__ mW1, const float* __restrict__ mb1,
               const float* __restrict__ mW2, const float* __restrict__ mb2,
               const float* __restrict__ pW1, const float* __restrict__ pb1,
               const float* __restrict__ pW2, const float* __restrict__ pb2,
               const float* __restrict__ pW3, const float* __restrict__ pb3,
               float* __restrict__ out, int npairs)
{
    // [0..342): segmented weights (replicated f32x2);
    // [344..472): PW2 transposed AND pre-scaled by pW3 (backward-only copy)
    __shared__ __align__(16) u64 wsm[472];
    {
        const float* srcs[12] = {mW0, mb0, mW1, mb1, mW2, mb2,
                                 pW1, pb1, pW2, pb2, pW3, pb3};
        const int offs[13] = {0, 16, 24, 88, 96, 128, 132, 164, 180, 308, 324, 340, 342};
        for (int idx = threadIdx.x; idx < 342; idx += blockDim.x) {
            int seg = 0;
            #pragma unroll
            for (int s2 = 0; s2 < 12; s2++)
                if (idx >= offs[s2 + 1]) seg = s2 + 1;
            float w = srcs[seg][idx - offs[seg]];
            wsm[idx] = pk(w, w);
        }
        // PW2T'[v*64 + pp*8 + q] = pW2[v, q, pp] * pW3[v, q]
        for (int idx = threadIdx.x; idx < 128; idx += blockDim.x) {
            int v = idx >> 6, rem = idx & 63;
            int pp = rem >> 3, q = rem & 7;
            float w = pW2[v * 64 + q * 8 + pp] * pW3[v * 8 + q];
            wsm[344 + idx] = pk(w, w);
        }
    }
    __syncthreads();

    const u64* W0   = wsm;         // 16 : [i*2+j]
    const u64* B0   = wsm + 16;    // 8
    const u64* W1   = wsm + 24;    // 64 : [i*8+j]
    const u64* B1   = wsm + 88;    // 8
    const u64* W2   = wsm + 96;    // 32 : [i*8+j]
    const u64* B2   = wsm + 128;   // 4
    const u64* PW1  = wsm + 132;   // 32 : [v*16+o*2+i]
    const u64* PB1  = wsm + 164;   // 16 : [v*8+o]
    const u64* PW2  = wsm + 180;   // 128: [v*64+q*8+p]
    const u64* PB2  = wsm + 308;   // 16 : [v*8+q]
    const u64* PW3  = wsm + 324;   // 16 : [v*8+p]
    const u64* PB3  = wsm + 340;   // 2  : [v]
    const u64* PW2T = wsm + 344;   // 128: [v*64+p*8+q], pre-scaled by w3_q

    const int tid = threadIdx.x;
    const int base   = blockIdx.x * NTHR + tid;
    const int stride = gridDim.x * NTHR;

    int pi[NPAIR];
    bool valid[NPAIR];
    u64 X0[NPAIR], X1[NPAIR];
    #pragma unroll
    for (int p = 0; p < NPAIR; p++) {
        pi[p] = base + p * stride;
        valid[p] = pi[p] < npairs;
        if (valid[p]) {
            float4 xx = reinterpret_cast<const float4*>(x)[pi[p]];
            X0[p] = pk(xx.x, xx.z);
            X1[p] = pk(xx.y, xx.w);
        } else {
            X0[p] = 0ULL; X1[p] = 0ULL;
        }
    }

    // ================= p nets (NV=2), forward + analytic backward =================
    u64 G0[NPAIR], G1[NPAIR];
    #pragma unroll
    for (int p = 0; p < NPAIR; p++) { G0[p] = 0ULL; G1[p] = 0ULL; }

    #pragma unroll
    for (int v = 0; v < 2; v++) {
        // f1 = tanh(x @ pW1^T + pb1)
        u64 f1[NPAIR][8];
        #pragma unroll
        for (int o = 0; o < 8; o++) {
            ulonglong2 w = lds128(&PW1[v * 16 + o * 2]);
            u64 b = PB1[v * 8 + o];
            #pragma unroll
            for (int p = 0; p < NPAIR; p++)
                f1[p][o] = tanh2(fma2(X1[p], w.y, fma2(X0[p], w.x, b)));
        }

        // f2 = tanh(f1 @ pW2^T + pb2)
        u64 f2[NPAIR][8];
        #pragma unroll
        for (int q = 0; q < 8; q++) {
            u64 a0[NPAIR], a1[NPAIR];
            u64 b = PB2[v * 8 + q];
            #pragma unroll
            for (int p = 0; p < NPAIR; p++) { a0[p] = b; a1[p] = 0ULL; }
            #pragma unroll
            for (int pp = 0; pp < 8; pp += 2) {
                ulonglong2 w = lds128(&PW2[v * 64 + q * 8 + pp]);
                #pragma unroll
                for (int p = 0; p < NPAIR; p++) {
                    a0[p] = fma2(f1[p][pp],     w.x, a0[p]);
                    a1[p] = fma2(f1[p][pp + 1], w.y, a1[p]);
                }
            }
            #pragma unroll
            for (int p = 0; p < NPAIR; p++) f2[p][q] = tanh2(add2(a0[p], a1[p]));
        }

        // z = f2 . pW3 + pb3 ; DS = 0.5 * s(1-s)  (independent of backward below)
        u64 DS[NPAIR];
        {
            u64 a0[NPAIR], a1[NPAIR];
            u64 b = PB3[v];
            #pragma unroll
            for (int p = 0; p < NPAIR; p++) { a0[p] = b; a1[p] = 0ULL; }
            #pragma unroll
            for (int pp = 0; pp < 8; pp += 2) {
                ulonglong2 w = lds128(&PW3[v * 8 + pp]);
                #pragma unroll
                for (int p = 0; p < NPAIR; p++) {
                    a0[p] = fma2(f2[p][pp],     w.x, a0[p]);
                    a1[p] = fma2(f2[p][pp + 1], w.y, a1[p]);
                }
            }
            #pragma unroll
            for (int p = 0; p < NPAIR; p++) {
                float za, zb; upk(add2(a0[p], a1[p]), za, zb);
                DS[p] = pk(ds_half(za), ds_half(zb));
            }
        }

        // gq'_q = (f2_q^2 - 1)   (w3 folded into PW2T; DS factored out;
        //                         sign cancels with gp's (f1^2-1))
        #pragma unroll
        for (int q = 0; q < 8; q++) {
            #pragma unroll
            for (int p = 0; p < NPAIR; p++)
                f2[p][q] = fma2(f2[p][q], f2[p][q], MONE2);
        }

        // PG_p = sum_pp [(sum_q gq'_q W2T'[pp,q]) * (f1_pp^2-1)] * pW1[pp,:]
        u64 PG0[NPAIR], PG1[NPAIR];
        #pragma unroll
        for (int p = 0; p < NPAIR; p++) { PG0[p] = 0ULL; PG1[p] = 0ULL; }
        #pragma unroll
        for (int pp = 0; pp < 8; pp++) {
            u64 a0[NPAIR], a1[NPAIR];
            #pragma unroll
            for (int p = 0; p < NPAIR; p++) { a0[p] = 0ULL; a1[p] = 0ULL; }
            #pragma unroll
            for (int q = 0; q < 8; q += 2) {
                ulonglong2 w = lds128(&PW2T[v * 64 + pp * 8 + q]);
                #pragma unroll
                for (int p = 0; p < NPAIR; p++) {
                    a0[p] = fma2(f2[p][q],     w.x, a0[p]);
                    a1[p] = fma2(f2[p][q + 1], w.y, a1[p]);
                }
            }
            ulonglong2 w1p = lds128(&PW1[v * 16 + pp * 2]);
            #pragma unroll
            for (int p = 0; p < NPAIR; p++) {
                u64 u1 = fma2(f1[p][pp], f1[p][pp], MONE2);
                u64 gpv = mul2(add2(a0[p], a1[p]), u1);
                PG0[p] = fma2(gpv, w1p.x, PG0[p]);
                PG1[p] = fma2(gpv, w1p.y, PG1[p]);
            }
        }
        // fold DS (incl. the 0.5 mean) in once per v
        #pragma unroll
        for (int p = 0; p < NPAIR; p++) {
            G0[p] = fma2(DS[p], PG0[p], G0[p]);
            G1[p] = fma2(DS[p], PG1[p], G1[p]);
        }
    }

    // ================= main net (last: only G carried across) =================
    u64 m2v[NPAIR], magA[NPAIR], magD[NPAIR];
    {
        u64 h0[NPAIR][8];
        #pragma unroll
        for (int i = 0; i < 8; i++) {
            ulonglong2 w = lds128(&W0[i * 2]);
            u64 b = B0[i];
            #pragma unroll
            for (int p = 0; p < NPAIR; p++)
                h0[p][i] = elu2(fma2(X1[p], w.y, fma2(X0[p], w.x, b)));
        }

        u64 h1[NPAIR][8];
        #pragma unroll
        for (int i = 0; i < 8; i++) {
            u64 a0[NPAIR], a1[NPAIR];
            u64 b = B1[i];
            #pragma unroll
            for (int p = 0; p < NPAIR; p++) { a0[p] = b; a1[p] = 0ULL; }
            #pragma unroll
            for (int j = 0; j < 8; j += 2) {
                ulonglong2 w = lds128(&W1[i * 8 + j]);
                #pragma unroll
                for (int p = 0; p < NPAIR; p++) {
                    a0[p] = fma2(h0[p][j],     w.x, a0[p]);
                    a1[p] = fma2(h0[p][j + 1], w.y, a1[p]);
                }
            }
            #pragma unroll
            for (int p = 0; p < NPAIR; p++) h1[p][i] = elu2(add2(a0[p], a1[p]));
        }

        u64 bb[NPAIR][4];
        #pragma unroll
        for (int i = 0; i < 4; i++) {
            u64 a0[NPAIR], a1[NPAIR];
            u64 b = B2[i];
            #pragma unroll
            for (int p = 0; p < NPAIR; p++) { a0[p] = b; a1[p] = 0ULL; }
            #pragma unroll
            for (int j = 0; j < 8; j += 2) {
                ulonglong2 w = lds128(&W2[i * 8 + j]);
                #pragma unroll
                for (int p = 0; p < NPAIR; p++) {
                    a0[p] = fma2(h1[p][j],     w.x, a0[p]);
                    a1[p] = fma2(h1[p][j + 1], w.y, a1[p]);
                }
            }
            #pragma unroll
            for (int p = 0; p < NPAIR; p++) bb[p][i] = add2(a0[p], a1[p]);
        }
        #pragma unroll
        for (int p = 0; p < NPAIR; p++) {
            m2v[p]  = fma2(bb[p][0], bb[p][1], mul2(bb[p][2], bb[p][3]));
            magA[p] = fma2(bb[p][0], bb[p][0], mul2(bb[p][2], bb[p][2]));
            magD[p] = fma2(bb[p][1], bb[p][1], mul2(bb[p][3], bb[p][3]));
        }
    }

    // out0 = magA*G0 + m2*G1; out1 = m2*G0 + magD*G1   (0.5 already in DS)
    #pragma unroll
    for (int p = 0; p < NPAIR; p++) {
        if (!valid[p]) continue;
        u64 o0 = fma2(magA[p], G0[p], mul2(m2v[p], G1[p]));
        u64 o1 = fma2(m2v[p], G0[p], mul2(magD[p], G1[p]));
        float a0, b0c, a1, b1c;
        upk(o0, a0, b0c);
        upk(o1, a1, b1c);
        reinterpret_cast<float4*>(out)[pi[p]] = make_float4(a0, a1, b0c, b1c);
    }
}

extern "C" void kernel_launch(void* const* d_in, const int* in_sizes, int n_in,
                              void* d_out, int out_size)
{
    const float* x   = (const float*)d_in[1];
    const float* mW0 = (const float*)d_in[2];
    const float* mb0 = (const float*)d_in[3];
    const float* mW1 = (const float*)d_in[4];
    const float* mb1 = (const float*)d_in[5];
    const float* mW2 = (const float*)d_in[6];
    const float* mb2 = (const float*)d_in[7];
    const float* pW1 = (const float*)d_in[8];
    const float* pb1 = (const float*)d_in[9];
    const float* pW2 = (const float*)d_in[10];
    const float* pb2 = (const float*)d_in[11];
    const float* pW3 = (const float*)d_in[12];
    const float* pb3 = (const float*)d_in[13];

    int B = in_sizes[1] / 2;       // x is (B, 2)
    int npairs = B / 2;
    int threads = NTHR;
    int tot_threads = (npairs + NPAIR - 1) / NPAIR;
    int blocks = (tot_threads + threads - 1) / threads;

    odefunc_kernel<<<blocks, threads>>>(x, mW0, mb0, mW1, mb1, mW2, mb2,
                                        pW1, pb1, pW2, pb2, pW3, pb3,
                                        (float*)d_out, npairs);
}